// round 7
// baseline (speedup 1.0000x reference)
#include <cuda_runtime.h>
#include <cuda_bf16.h>
#include <cstdint>

#define NSTATE (1u << 23)

__device__ float g_scratch[1u << 24];
__device__ __nv_bfloat16 g_ubf[262144];   // 4 gates x 4 matrices x 16384 bf16

#define SMEM_BYTES 196608u
#define SGN 0x80008000u

// gates 0-2: U tiles at [0,131072) (4 x 32768), state A buffers at 131072 + buf*32768 (4 x 8192)
#define AL_OFF 131072u
// gate 3: U-half tiles at [0,65536) (4 x 16384), state B buffers at 65536 + buf*65536 (4 x 16384)
#define BH_OFF 65536u

__device__ __forceinline__ uint32_t smem_u32(const void* p) {
    uint32_t a;
    asm("{ .reg .u64 t; cvta.to.shared.u64 t, %1; cvt.u32.u64 %0, t; }" : "=r"(a) : "l"(p));
    return a;
}

#define CPASYNC16(saddr, gptr)                                                  \
    asm volatile("cp.async.cg.shared.global [%0], [%1], 16;"                    \
        :: "r"(saddr), "l"(gptr) : "memory")

#define LDM4(r, addr)                                                           \
    asm volatile("ldmatrix.sync.aligned.m8n8.x4.shared.b16 {%0,%1,%2,%3}, [%4];"\
        : "=r"((r)[0]), "=r"((r)[1]), "=r"((r)[2]), "=r"((r)[3]) : "r"(addr))

#define LDM4T(r, addr)                                                          \
    asm volatile("ldmatrix.sync.aligned.m8n8.x4.trans.shared.b16 {%0,%1,%2,%3}, [%4];"\
        : "=r"((r)[0]), "=r"((r)[1]), "=r"((r)[2]), "=r"((r)[3]) : "r"(addr))

#define MMA(C, A, b0v, b1v)                                                     \
    asm volatile("mma.sync.aligned.m16n8k16.row.col.f32.bf16.bf16.f32 "         \
        "{%0,%1,%2,%3}, {%4,%5,%6,%7}, {%8,%9}, {%0,%1,%2,%3};"                 \
        : "+f"((C)[0]), "+f"((C)[1]), "+f"((C)[2]), "+f"((C)[3])                \
        : "r"((A)[0]), "r"((A)[1]), "r"((A)[2]), "r"((A)[3]), "r"(b0v), "r"(b1v))

// B fragment selectors: j = g*2 + j2 -> bfg[g][mat][j2] / [j2+2]
#define B0(j, m) bfg[(j) >> 1][m][(j) & 1]
#define B1(j, m) bfg[(j) >> 1][m][((j) & 1) + 2]

// Issue one term into all 4 chains of an accumulator set (round-robin ILP).
#define R4(ACC, AOP, M)                                                         \
    MMA(ACC[0], AOP, B0(0, M), B1(0, M));                                       \
    MMA(ACC[1], AOP, B0(1, M), B1(1, M));                                       \
    MMA(ACC[2], AOP, B0(2, M), B1(2, M));                                       \
    MMA(ACC[3], AOP, B0(3, M), B1(3, M));

// 96 MMAs, alternating acc1/acc0 sets so 8 chains stay in flight.
// ch1 = A_r*B_r - A_i*B_i ; ch0 = A_i*B_r + A_r*B_i (hi*hi + hi*lo + lo*hi each)
#define MMA96()                                                                 \
    R4(acc1, af[0], 0)  R4(acc0, af[2], 0)                                      \
    R4(acc1, af[0], 1)  R4(acc0, af[2], 1)                                      \
    R4(acc1, af[1], 0)  R4(acc0, af[3], 0)                                      \
    R4(acc1, naf2,  2)  R4(acc0, af[0], 2)                                      \
    R4(acc1, naf2,  3)  R4(acc0, af[0], 3)                                      \
    R4(acc1, naf3,  2)  R4(acc0, af[1], 2)

// fp32 x8 -> bf16 hi (16B) + bf16 lo (16B)
__device__ __forceinline__ void cvt8(float4 x, float4 y, uint4* hi, uint4* lo) {
    float f[8] = {x.x, x.y, x.z, x.w, y.x, y.y, y.z, y.w};
    uint32_t h[8], l[8];
    #pragma unroll
    for (int i = 0; i < 8; ++i) {
        __nv_bfloat16 hb = __float2bfloat16(f[i]);
        h[i] = (uint32_t)__bfloat16_as_ushort(hb);
        l[i] = (uint32_t)__bfloat16_as_ushort(__float2bfloat16(f[i] - __bfloat162float(hb)));
    }
    *hi = make_uint4(h[0] | (h[1] << 16), h[2] | (h[3] << 16),
                     h[4] | (h[5] << 16), h[6] | (h[7] << 16));
    *lo = make_uint4(l[0] | (l[1] << 16), l[2] | (l[3] << 16),
                     l[4] | (l[5] << 16), l[6] | (l[7] << 16));
}

// ---------------------------------------------------------------------------
__global__ void prep_u(const float* __restrict__ U)
{
    const int i = blockIdx.x * 256 + threadIdx.x;   // 131072
    const int a = i & 127, k = (i >> 7) & 127, c = (i >> 14) & 1, g = i >> 15;
    const float x = U[i];
    const __nv_bfloat16 hi = __float2bfloat16(x);
    const __nv_bfloat16 lo = __float2bfloat16(x - __bfloat162float(hi));
    const int h = k * 128 + (((a >> 3) ^ (k & 7)) << 3) + (a & 7);
    g_ubf[g * 65536 + (c * 2 + 0) * 16384 + h] = hi;
    g_ubf[g * 65536 + (c * 2 + 1) * 16384 + h] = lo;
}

// ---------------------------------------------------------------------------
// Gates 0-2, persistent: U resident in SMEM; 32-row state chunks double-buffered.
__global__ void __launch_bounds__(256, 1)
gate_lowp(const float* __restrict__ in, float* __restrict__ out,
          const __nv_bfloat16* __restrict__ img)
{
    extern __shared__ char smem[];
    const uint32_t sb = smem_u32(smem);
    const int t = threadIdx.x, lane = t & 31, w = t >> 5;

    // stage U image once (128KB, pre-swizzled)
    {
        const uint4* src = (const uint4*)img;
        #pragma unroll
        for (int j = 0; j < 32; ++j) {
            const int idx = t + 256 * j;
            CPASYNC16(sb + (uint32_t)idx * 16u, src + idx);
        }
        asm volatile("cp.async.commit_group;" ::: "memory");
    }

    int item = blockIdx.x;
    // first chunk convert (direct)
    {
        const size_t base = (size_t)item * 4096;
        #pragma unroll
        for (int s = 0; s < 4; ++s) {
            const int slot = t + 256 * s;
            const int c = slot & 15, r = (slot >> 4) & 31, ch = slot >> 9;
            const float4* p = (const float4*)(in + (size_t)ch * NSTATE + base + r * 128 + c * 8);
            uint4 hi, lo;
            cvt8(p[0], p[1], &hi, &lo);
            char* wp = smem + AL_OFF + (ch * 2) * 8192 + r * 256 + ((c ^ (r & 7)) * 16);
            *(uint4*)wp = hi;
            *(uint4*)(wp + 8192) = lo;
        }
    }
    asm volatile("cp.async.wait_group 0;" ::: "memory");
    __syncthreads();

    const int mrow0 = (w & 1) * 16, ncol0 = (w >> 1) * 32;
    const int ar = mrow0 + (lane & 15), acl = lane >> 4, ar7 = ar & 7;
    const int br_off = lane & 15, bcl = lane >> 4;
    const int rg = lane >> 2, tg = lane & 3;

    uint32_t buf = 0;
    for (; item < 2048; item += 148) {
        const int next = item + 148;
        const bool hasnext = next < 2048;
        float4 stg[8];
        if (hasnext) {
            const size_t base = (size_t)next * 4096;
            #pragma unroll
            for (int s = 0; s < 4; ++s) {
                const int slot = t + 256 * s;
                const int c = slot & 15, r = (slot >> 4) & 31, ch = slot >> 9;
                const float4* p = (const float4*)(in + (size_t)ch * NSTATE + base + r * 128 + c * 8);
                stg[2 * s] = p[0];
                stg[2 * s + 1] = p[1];
            }
        }

        float acc0[4][4], acc1[4][4];
        #pragma unroll
        for (int j = 0; j < 4; ++j)
            #pragma unroll
            for (int q = 0; q < 4; ++q) { acc0[j][q] = 0.f; acc1[j][q] = 0.f; }

        const uint32_t abase = sb + AL_OFF + buf * 32768u + (uint32_t)ar * 256u;
        #pragma unroll 1
        for (int ks = 0; ks < 8; ++ks) {
            uint32_t af[4][4], naf2[4], naf3[4];
            const uint32_t aa = abase + (uint32_t)(((ks * 2 + acl) ^ ar7) << 4);
            LDM4(af[0], aa);
            LDM4(af[1], aa + 8192);
            LDM4(af[2], aa + 16384);
            LDM4(af[3], aa + 24576);

            uint32_t bfg[2][4][4];
            #pragma unroll
            for (int g = 0; g < 2; ++g) {
                const int row = ncol0 + g * 16 + br_off;
                const uint32_t ba = sb + (uint32_t)row * 256u
                                  + (uint32_t)((((ks * 2 + bcl) ^ (row & 7))) << 4);
                LDM4(bfg[g][0], ba);
                LDM4(bfg[g][1], ba + 32768);
                LDM4(bfg[g][2], ba + 65536);
                LDM4(bfg[g][3], ba + 98304);
            }
            #pragma unroll
            for (int q = 0; q < 4; ++q) { naf2[q] = af[2][q] ^ SGN; naf3[q] = af[3][q] ^ SGN; }

            MMA96()
        }

        if (hasnext) {
            #pragma unroll
            for (int s = 0; s < 4; ++s) {
                const int slot = t + 256 * s;
                const int c = slot & 15, r = (slot >> 4) & 31, ch = slot >> 9;
                uint4 hi, lo;
                cvt8(stg[2 * s], stg[2 * s + 1], &hi, &lo);
                char* wp = smem + AL_OFF + (buf ^ 1u) * 32768u + (ch * 2) * 8192 + r * 256
                         + ((c ^ (r & 7)) * 16);
                *(uint4*)wp = hi;
                *(uint4*)(wp + 8192) = lo;
            }
        }

        {
            const size_t row0 = (size_t)item * 32 + mrow0 + rg;
            float* o0 = out;
            float* o1 = out + NSTATE;
            #pragma unroll
            for (int j = 0; j < 4; ++j) {
                const int n = ncol0 + j * 8 + tg * 2;
                *(float2*)(o0 + row0 * 128 + n)       = make_float2(acc0[j][0], acc0[j][1]);
                *(float2*)(o0 + (row0 + 8) * 128 + n) = make_float2(acc0[j][2], acc0[j][3]);
                *(float2*)(o1 + row0 * 128 + n)       = make_float2(acc1[j][0], acc1[j][1]);
                *(float2*)(o1 + (row0 + 8) * 128 + n) = make_float2(acc1[j][2], acc1[j][3]);
            }
        }
        __syncthreads();
        buf ^= 1u;
    }
}

// ---------------------------------------------------------------------------
// Gate 3, persistent: A = U k-half resident; B = state (128a x 64l) double-buffered.
__global__ void __launch_bounds__(256, 1)
gate_highp(const float* __restrict__ in, float* __restrict__ out,
           const __nv_bfloat16* __restrict__ img)
{
    extern __shared__ char smem[];
    const uint32_t sb = smem_u32(smem);
    const int t = threadIdx.x, lane = t & 31, w = t >> 5;
    const int khalf = blockIdx.x & 1;
    const int pairid = blockIdx.x >> 1;   // 0..73

    // stage U k-half once (64KB, pre-swizzled; 64 rows per matrix)
    {
        const uint4* src = (const uint4*)img;
        #pragma unroll
        for (int j = 0; j < 16; ++j) {
            const int idx = t + 256 * j;              // 0..4095
            const int m = idx >> 10, within = idx & 1023;
            CPASYNC16(sb + (uint32_t)idx * 16u, src + m * 2048 + khalf * 1024 + within);
        }
        asm volatile("cp.async.commit_group;" ::: "memory");
    }

    int widx = pairid;                    // over 1024 = 512 chunks x 2 l-halves
    // first item convert (direct, 8 slots)
    {
        const int chunk = widx >> 1, lh = widx & 1;
        const size_t cb = (size_t)chunk * 16384;
        #pragma unroll
        for (int s = 0; s < 8; ++s) {
            const int slot = t + 256 * s;
            const int c = slot & 7, a = (slot >> 3) & 127, ch = slot >> 10;
            const float4* p = (const float4*)(in + (size_t)ch * NSTATE + cb + a * 128 + lh * 64 + c * 8);
            uint4 hi, lo;
            cvt8(p[0], p[1], &hi, &lo);
            char* wp = smem + BH_OFF + (ch * 2) * 16384 + a * 128 + ((c ^ (a & 7)) * 16);
            *(uint4*)wp = hi;
            *(uint4*)(wp + 16384) = lo;
        }
    }
    asm volatile("cp.async.wait_group 0;" ::: "memory");
    __syncthreads();

    const int mrow0 = (w & 3) * 16, ncol0 = (w >> 2) * 32;
    const int ar = mrow0 + (lane & 15), acl = lane >> 4, ar7 = ar & 7;
    const int br_off = (lane & 7) + ((lane & 16) >> 1), bcl = (lane >> 3) & 1;
    const int rg = lane >> 2, tg = lane & 3;
    const uint32_t abase = sb + (uint32_t)ar * 256u;

    uint32_t buf = 0;
    for (; widx < 1024; widx += 74) {
        const int chunk = widx >> 1, lh = widx & 1;
        const size_t cb = (size_t)chunk * 16384;
        const int nwidx = widx + 74;
        const bool hasnext = nwidx < 1024;
        const int nchunk = nwidx >> 1, nlh = nwidx & 1;
        const size_t ncb = (size_t)nchunk * 16384;

        float4 stg[8];                    // slots 0..3 staged; 4..7 loaded after MMA
        if (hasnext) {
            #pragma unroll
            for (int s = 0; s < 4; ++s) {
                const int slot = t + 256 * s;
                const int c = slot & 7, a = (slot >> 3) & 127, ch = slot >> 10;
                const float4* p = (const float4*)(in + (size_t)ch * NSTATE + ncb + a * 128 + nlh * 64 + c * 8);
                stg[2 * s] = p[0];
                stg[2 * s + 1] = p[1];
            }
        }

        float acc0[4][4], acc1[4][4];
        #pragma unroll
        for (int j = 0; j < 4; ++j)
            #pragma unroll
            for (int q = 0; q < 4; ++q) { acc0[j][q] = 0.f; acc1[j][q] = 0.f; }

        const uint32_t bbuf = sb + BH_OFF + buf * 65536u;
        #pragma unroll 1
        for (int ks = 0; ks < 8; ++ks) {
            uint32_t af[4][4], naf2[4], naf3[4];
            const uint32_t aa = abase + (uint32_t)(((ks * 2 + acl) ^ ar7) << 4);
            LDM4(af[0], aa);
            LDM4(af[1], aa + 16384);
            LDM4(af[2], aa + 32768);
            LDM4(af[3], aa + 49152);

            uint32_t bfg[2][4][4];
            #pragma unroll
            for (int g = 0; g < 2; ++g) {
                const int row = ks * 16 + br_off;
                const int cidx = ((ncol0 + g * 16) >> 3) + bcl;
                const uint32_t ba = bbuf + (uint32_t)row * 128u
                                  + (uint32_t)((cidx ^ (row & 7)) << 4);
                LDM4T(bfg[g][0], ba);
                LDM4T(bfg[g][1], ba + 16384);
                LDM4T(bfg[g][2], ba + 32768);
                LDM4T(bfg[g][3], ba + 49152);
            }
            #pragma unroll
            for (int q = 0; q < 4; ++q) { naf2[q] = af[2][q] ^ SGN; naf3[q] = af[3][q] ^ SGN; }

            MMA96()
        }

        if (hasnext) {
            #pragma unroll
            for (int s = 0; s < 4; ++s) {
                const int slot = t + 256 * s;
                const int c = slot & 7, a = (slot >> 3) & 127, ch = slot >> 10;
                uint4 hi, lo;
                cvt8(stg[2 * s], stg[2 * s + 1], &hi, &lo);
                char* wp = smem + BH_OFF + (buf ^ 1u) * 65536u + (ch * 2) * 16384 + a * 128
                         + ((c ^ (a & 7)) * 16);
                *(uint4*)wp = hi;
                *(uint4*)(wp + 16384) = lo;
            }
            #pragma unroll
            for (int s = 4; s < 8; ++s) {
                const int slot = t + 256 * s;
                const int c = slot & 7, a = (slot >> 3) & 127, ch = slot >> 10;
                const float4* p = (const float4*)(in + (size_t)ch * NSTATE + ncb + a * 128 + nlh * 64 + c * 8);
                uint4 hi, lo;
                cvt8(p[0], p[1], &hi, &lo);
                char* wp = smem + BH_OFF + (buf ^ 1u) * 65536u + (ch * 2) * 16384 + a * 128
                         + ((c ^ (a & 7)) * 16);
                *(uint4*)wp = hi;
                *(uint4*)(wp + 16384) = lo;
            }
        }

        {
            const size_t row0 = (size_t)khalf * 64 + mrow0 + rg;
            float* o0 = out + cb;
            float* o1 = out + NSTATE + cb;
            #pragma unroll
            for (int j = 0; j < 4; ++j) {
                const int n = lh * 64 + ncol0 + j * 8 + tg * 2;
                *(float2*)(o0 + row0 * 128 + n)       = make_float2(acc0[j][0], acc0[j][1]);
                *(float2*)(o0 + (row0 + 8) * 128 + n) = make_float2(acc0[j][2], acc0[j][3]);
                *(float2*)(o1 + row0 * 128 + n)       = make_float2(acc1[j][0], acc1[j][1]);
                *(float2*)(o1 + (row0 + 8) * 128 + n) = make_float2(acc1[j][2], acc1[j][3]);
            }
        }
        __syncthreads();
        buf ^= 1u;
    }
}

// ---------------------------------------------------------------------------
extern "C" void kernel_launch(void* const* d_in, const int* in_sizes, int n_in,
                              void* d_out, int out_size)
{
    const float* state = (const float*)d_in[0];
    const float* U     = (const float*)d_in[1];
    if (n_in >= 2 && in_sizes[0] < in_sizes[1]) {
        const float* tmp = state; state = U; U = tmp;
    }
    float* out = (float*)d_out;

    float* scratch = nullptr;
    cudaGetSymbolAddress((void**)&scratch, g_scratch);
    __nv_bfloat16* ubf = nullptr;
    cudaGetSymbolAddress((void**)&ubf, g_ubf);

    cudaFuncSetAttribute(gate_lowp,  cudaFuncAttributeMaxDynamicSharedMemorySize, (int)SMEM_BYTES);
    cudaFuncSetAttribute(gate_highp, cudaFuncAttributeMaxDynamicSharedMemorySize, (int)SMEM_BYTES);

    prep_u<<<512, 256>>>(U);
    gate_lowp<<<148, 256, SMEM_BYTES>>>(state,   scratch, ubf);            // gate 0
    gate_lowp<<<148, 256, SMEM_BYTES>>>(scratch, out,     ubf + 65536);    // gate 1
    gate_lowp<<<148, 256, SMEM_BYTES>>>(out,     scratch, ubf + 131072);   // gate 2
    gate_highp<<<148, 256, SMEM_BYTES>>>(scratch, out,    ubf + 196608);   // gate 3
}